// round 16
// baseline (speedup 1.0000x reference)
#include <cuda_runtime.h>
#include <cuda_bf16.h>

// SSIM loss, round 16: R15 base (128x16 tiles, NOUT=8 packed ring V, 8-out H,
// 64 regs, 4 blocks/SM) with phase-V loads batched 2 rows at a time:
// 4 independent LDGs per stall point (MLP 2->4), 9 stall points instead of 18.

#define TW 128
#define TH 16
#define RAD 5
#define INW 138         // TW + 2*RAD
#define HBW2 142        // hb row stride in u64 (1136B)
#define HW 512
#define PLANE_ELEMS (512 * 512)
#define NBLOCKS 6144

#define W0 0.00102838f
#define W1 0.00759877f
#define W2 0.03600077f
#define W3 0.10936070f
#define W4 0.21300554f
#define W5 0.26601173f

typedef unsigned long long ull;

__device__ float g_partials[NBLOCKS];
__device__ unsigned int g_counter = 0;

__device__ __forceinline__ ull f2pack(float lo, float hi) {
    ull d;
    asm("mov.b64 %0, {%1, %2};" : "=l"(d) : "f"(lo), "f"(hi));
    return d;
}
__device__ __forceinline__ void f2unpack(float& lo, float& hi, ull v) {
    asm("mov.b64 {%0, %1}, %2;" : "=f"(lo), "=f"(hi) : "l"(v));
}
__device__ __forceinline__ ull fma2(ull a, ull b, ull c) {
    ull d;
    asm("fma.rn.f32x2 %0, %1, %2, %3;" : "=l"(d) : "l"(a), "l"(b), "l"(c));
    return d;
}
#define WIDX(k) ((k) < 6 ? (k) : 10 - (k))

// Vertical FIR over one column: NOUT outputs, NOUT+10 loads (NLOAD even),
// loads issued two rows (4 LDGs) per batch for MLP.
template<bool INTERIOR, int NOUT>
__device__ __forceinline__ void vcol(
    const float* __restrict__ prow, const float* __restrict__ trow,
    bool xok, int gybase, int c, int obase,
    ull* __restrict__ hb01, ull* __restrict__ hb23, const ull* __restrict__ Wb)
{
    constexpr int NLOAD = NOUT + 10;    // even for even NOUT
    ull a01[NOUT], a23[NOUT];
#pragma unroll
    for (int s = 0; s < NOUT; s++) { a01[s] = 0ull; a23[s] = 0ull; }

#pragma unroll
    for (int rb = 0; rb < NLOAD; rb += 2) {
        float pv[2], tv[2];
        // Issue 4 independent loads back-to-back.
#pragma unroll
        for (int h = 0; h < 2; h++) {
            int rr = rb + h;
            if (INTERIOR) {
                pv[h] = __ldg(prow + rr * HW);
                tv[h] = __ldg(trow + rr * HW);
            } else {
                int gy = gybase + rr;
                pv[h] = 0.f; tv[h] = 0.f;
                if (xok && gy >= 0 && gy < HW) {
                    pv[h] = __ldg(prow + rr * HW);
                    tv[h] = __ldg(trow + rr * HW);
                }
            }
        }
        // Process both rows.
#pragma unroll
        for (int h = 0; h < 2; h++) {
            int rr = rb + h;
            float p = pv[h];
            float t = tv[h];
            float sv = p + t;
            float dv = p - t;
            ull pt = f2pack(p, t);
            ull sd = f2pack(sv * sv, dv * dv);
#pragma unroll
            for (int j = 0; j < NOUT; j++) {
                int k = rr - j;
                if (k >= 0 && k <= 10) {
                    a01[j] = fma2(Wb[WIDX(k)], pt, a01[j]);
                    a23[j] = fma2(Wb[WIDX(k)], sd, a23[j]);
                }
            }
            if (rr >= 10) {
                int j = rr - 10;
                int row = obase + j;
                hb01[row * HBW2 + c] = a01[j];
                hb23[row * HBW2 + c] = a23[j];
            }
        }
    }
}

__global__ __launch_bounds__(256, 4) void ssim_main_kernel(
    const float* __restrict__ pred,
    const float* __restrict__ target,
    float* __restrict__ out,
    float inv_count)
{
    extern __shared__ __align__(16) ull smem_raw[];
    ull* hb01 = smem_raw;                   // [16][142] u64 = 18176 B
    ull* hb23 = smem_raw + TH * HBW2;       // [16][142] u64 = 18176 B
    __shared__ float red[8];
    __shared__ bool s_last;

    const int tid = threadIdx.x;
    const int x0 = blockIdx.x * TW;
    const int y0 = blockIdx.y * TH;
    const size_t plane_off = (size_t)blockIdx.z * PLANE_ELEMS;
    const float* __restrict__ pp = pred + plane_off;
    const float* __restrict__ tt = target + plane_off;

    ull Wb[6];
    Wb[0] = f2pack(W0, W0);  Wb[1] = f2pack(W1, W1);
    Wb[2] = f2pack(W2, W2);  Wb[3] = f2pack(W3, W3);
    Wb[4] = f2pack(W4, W4);  Wb[5] = f2pack(W5, W5);

    const bool interior =
        (x0 >= RAD) && (x0 + TW + RAD <= HW) && (y0 >= RAD) && (y0 + TH + RAD <= HW);

    // ---- Phase V: 256 full 8-out items (1/thread); the 20 leftover columns
    // become 80 quarter-items (2 outputs) on threads 176..255 ----
    {
        int g = tid / INW;               // 0 or 1 (8-row group)
        int c = tid - g * INW;
        int ob = 8 * g;
        int gyb = y0 + ob - RAD;
        int gx = x0 - RAD + c;
        bool xok = interior || ((gx >= 0) && (gx < HW));
        const float* prow = pp + (size_t)gyb * HW + gx;
        const float* trow = tt + (size_t)gyb * HW + gx;
        if (interior) vcol<true , 8>(prow, trow, xok, gyb, c, ob, hb01, hb23, Wb);
        else          vcol<false, 8>(prow, trow, xok, gyb, c, ob, hb01, hb23, Wb);

        if (tid >= 176) {
            int hh = tid - 176;              // 0..79
            int c2 = 118 + (hh >> 2);        // column 118..137
            int ob2 = 8 + 2 * (hh & 3);      // rows 8,10,12,14 (+1)
            int gyb2 = y0 + ob2 - RAD;
            int gx2 = x0 - RAD + c2;
            bool xok2 = interior || ((gx2 >= 0) && (gx2 < HW));
            const float* prow2 = pp + (size_t)gyb2 * HW + gx2;
            const float* trow2 = tt + (size_t)gyb2 * HW + gx2;
            if (interior) vcol<true , 2>(prow2, trow2, xok2, gyb2, c2, ob2, hb01, hb23, Wb);
            else          vcol<false, 2>(prow2, trow2, xok2, gyb2, c2, ob2, hb01, hb23, Wb);
        }
    }
    __syncthreads();

    // ---- Phase H: 8 outputs/thread; 16 rows x 16 x-groups = 256 items ----
    const float C1 = 0.0001f;
    const float C2 = 0.0009f;
    float local = 0.f;
    {
        int r = tid & 15;                   // row
        int xg = tid >> 4;                  // 0..15
        int Xb = xg << 3;                   // x base (even)
        const ull* rb01 = hb01 + r * HBW2 + Xb;
        const ull* rb23 = hb23 + r * HBW2 + Xb;

        ull acc01[8], acc23[8];
#pragma unroll
        for (int j = 0; j < 8; j++) { acc01[j] = 0ull; acc23[j] = 0ull; }

#pragma unroll
        for (int q = 0; q < 9; q++) {        // 18 input positions
            ulonglong2 u01 = *(const ulonglong2*)(rb01 + 2 * q);
            ulonglong2 u23 = *(const ulonglong2*)(rb23 + 2 * q);
#pragma unroll
            for (int half = 0; half < 2; half++) {
                int i = 2 * q + half;
                ull v01 = half ? u01.y : u01.x;
                ull v23 = half ? u23.y : u23.x;
#pragma unroll
                for (int j = 0; j < 8; j++) {
                    int k = i - j;
                    if (k >= 0 && k <= 10) {
                        acc01[j] = fma2(Wb[WIDX(k)], v01, acc01[j]);
                        acc23[j] = fma2(Wb[WIDX(k)], v23, acc23[j]);
                    }
                }
            }
        }

#pragma unroll
        for (int j = 0; j < 8; j++) {
            float m1, m2, cs, cd;
            f2unpack(m1, m2, acc01[j]);
            f2unpack(cs, cd, acc23[j]);
            float m1s = m1 * m1;
            float m2s = m2 * m2;
            float m12 = m1 * m2;
            float ept   = 0.25f * (cs - cd);
            float epptt = 0.5f  * (cs + cd);
            float s12  = ept - m12;
            float ssum = epptt - m1s - m2s;
            float num = (2.0f * m12 + C1) * (2.0f * s12 + C2);
            float den = (m1s + m2s + C1) * (ssum + C2);
            local += __fdividef(num, den);
        }
    }

    // ---- Block reduction -> partial; last block reduces globally ----
#pragma unroll
    for (int off = 16; off > 0; off >>= 1)
        local += __shfl_down_sync(0xffffffffu, local, off);
    if ((tid & 31) == 0) red[tid >> 5] = local;
    __syncthreads();
    if (tid == 0) {
        float v = red[0] + red[1] + red[2] + red[3]
                + red[4] + red[5] + red[6] + red[7];
        int bid = (blockIdx.z * gridDim.y + blockIdx.y) * gridDim.x + blockIdx.x;
        g_partials[bid] = v;
        __threadfence();
        unsigned int n = atomicAdd(&g_counter, 1u);
        s_last = (n == NBLOCKS - 1u);
    }
    __syncthreads();

    if (s_last) {
        __threadfence();
        __shared__ double dred[8];
        const float4* __restrict__ p4 = (const float4*)g_partials;
        double acc = 0.0;
#pragma unroll
        for (int i = 0; i < NBLOCKS / 4 / 256; i++) {   // 6 iterations
            float4 v = p4[i * 256 + tid];
            acc += (double)v.x + (double)v.y + (double)v.z + (double)v.w;
        }
#pragma unroll
        for (int off = 16; off > 0; off >>= 1)
            acc += __shfl_down_sync(0xffffffffu, acc, off);
        if ((tid & 31) == 0) dred[tid >> 5] = acc;
        __syncthreads();
        if (tid == 0) {
            double s = dred[0] + dred[1] + dred[2] + dred[3]
                     + dred[4] + dred[5] + dred[6] + dred[7];
            out[0] = 1.0f - (float)(s * (double)inv_count);
            g_counter = 0;
        }
    }
}

extern "C" void kernel_launch(void* const* d_in, const int* in_sizes, int n_in,
                              void* d_out, int out_size) {
    const float* pred = (const float*)d_in[0];
    const float* target = (const float*)d_in[1];
    float* out = (float*)d_out;

    const int total = in_sizes[0];                 // N*C*H*W
    const int nplanes = total / PLANE_ELEMS;       // 48

    const size_t smem = sizeof(ull) * 2 * TH * HBW2;   // 36352 B
    cudaFuncSetAttribute(ssim_main_kernel,
                         cudaFuncAttributeMaxDynamicSharedMemorySize, (int)smem);

    dim3 grid(HW / TW, HW / TH, nplanes);          // (4, 32, 48) = 6144 blocks
    ssim_main_kernel<<<grid, 256, smem>>>(pred, target, out, 1.0f / (float)total);
}

// round 17
// speedup vs baseline: 1.0403x; 1.0403x over previous
#include <cuda_runtime.h>
#include <cuda_bf16.h>
#include <cuda_fp16.h>

// SSIM loss, round 17: R15 base (128x16 tiles, NOUT=8 packed f32x2 ring V,
// 64 regs, 4 blocks/SM) with the hb intermediate stored as fp16 half2 and the
// H conv done in HFMA2. Halves STS + H LDS bytes at equal fma-pipe throughput.
// fp16 weight-sum deviation (1.00016403) corrected by INV_S in the epilogue.

#define TW 128
#define TH 16
#define RAD 5
#define INW 138         // TW + 2*RAD
#define HBW 148         // hb row stride in u32 units (592B; 37 chunks, odd)
#define HW 512
#define PLANE_ELEMS (512 * 512)
#define NBLOCKS 6144

#define W0 0.00102838f
#define W1 0.00759877f
#define W2 0.03600077f
#define W3 0.10936070f
#define W4 0.21300554f
#define W5 0.26601173f
// 1 / (sum of fp16-rounded 11-tap weights) = 1 / 1.00016403
#define INV_S 0.99983600f

typedef unsigned long long ull;

__device__ float g_partials[NBLOCKS];
__device__ unsigned int g_counter = 0;

__device__ __forceinline__ ull f2pack(float lo, float hi) {
    ull d;
    asm("mov.b64 %0, {%1, %2};" : "=l"(d) : "f"(lo), "f"(hi));
    return d;
}
__device__ __forceinline__ void f2unpack(float& lo, float& hi, ull v) {
    asm("mov.b64 {%0, %1}, %2;" : "=f"(lo), "=f"(hi) : "l"(v));
}
__device__ __forceinline__ ull fma2(ull a, ull b, ull c) {
    ull d;
    asm("fma.rn.f32x2 %0, %1, %2, %3;" : "=l"(d) : "l"(a), "l"(b), "l"(c));
    return d;
}
// pack two f32 into f16x2: result = {lo, hi}
__device__ __forceinline__ unsigned int f32x2_to_f16x2(ull v) {
    float lo, hi;
    f2unpack(lo, hi, v);
    unsigned int r;
    asm("cvt.rn.f16x2.f32 %0, %1, %2;" : "=r"(r) : "f"(hi), "f"(lo));
    return r;
}
#define WIDX(k) ((k) < 6 ? (k) : 10 - (k))

// Vertical FIR over one column: NOUT outputs, NOUT+10 loads. fp32 math,
// outputs converted to half2 for smem.
template<bool INTERIOR, int NOUT>
__device__ __forceinline__ void vcol(
    const float* __restrict__ prow, const float* __restrict__ trow,
    bool xok, int gybase, int c, int obase,
    unsigned int* __restrict__ hb01, unsigned int* __restrict__ hb23,
    const ull* __restrict__ Wb)
{
    constexpr int NLOAD = NOUT + 10;
    ull a01[NOUT], a23[NOUT];
#pragma unroll
    for (int s = 0; s < NOUT; s++) { a01[s] = 0ull; a23[s] = 0ull; }

#pragma unroll
    for (int rr = 0; rr < NLOAD; rr++) {
        float p, t;
        if (INTERIOR) {
            p = __ldg(prow + rr * HW);
            t = __ldg(trow + rr * HW);
        } else {
            int gy = gybase + rr;
            p = 0.f; t = 0.f;
            if (xok && gy >= 0 && gy < HW) {
                p = __ldg(prow + rr * HW);
                t = __ldg(trow + rr * HW);
            }
        }
        float sv = p + t;
        float dv = p - t;
        ull pt = f2pack(p, t);
        ull sd = f2pack(sv * sv, dv * dv);
#pragma unroll
        for (int j = 0; j < NOUT; j++) {
            int k = rr - j;
            if (k >= 0 && k <= 10) {
                a01[j] = fma2(Wb[WIDX(k)], pt, a01[j]);
                a23[j] = fma2(Wb[WIDX(k)], sd, a23[j]);
            }
        }
        if (rr >= 10) {
            int j = rr - 10;
            int row = obase + j;
            hb01[row * HBW + c] = f32x2_to_f16x2(a01[j]);
            hb23[row * HBW + c] = f32x2_to_f16x2(a23[j]);
        }
    }
}

__global__ __launch_bounds__(256, 4) void ssim_main_kernel(
    const float* __restrict__ pred,
    const float* __restrict__ target,
    float* __restrict__ out,
    float inv_count)
{
    extern __shared__ __align__(16) unsigned int smem_raw[];
    unsigned int* hb01 = smem_raw;               // [16][148] u32 = 9472 B
    unsigned int* hb23 = smem_raw + TH * HBW;    // [16][148] u32 = 9472 B
    __shared__ float red[8];
    __shared__ bool s_last;

    const int tid = threadIdx.x;
    const int x0 = blockIdx.x * TW;
    const int y0 = blockIdx.y * TH;
    const size_t plane_off = (size_t)blockIdx.z * PLANE_ELEMS;
    const float* __restrict__ pp = pred + plane_off;
    const float* __restrict__ tt = target + plane_off;

    // fp32 packed weights for V
    ull Wb[6];
    Wb[0] = f2pack(W0, W0);  Wb[1] = f2pack(W1, W1);
    Wb[2] = f2pack(W2, W2);  Wb[3] = f2pack(W3, W3);
    Wb[4] = f2pack(W4, W4);  Wb[5] = f2pack(W5, W5);
    // fp16 broadcast weights for H
    __half2 Wh[6];
    Wh[0] = __float2half2_rn(W0);  Wh[1] = __float2half2_rn(W1);
    Wh[2] = __float2half2_rn(W2);  Wh[3] = __float2half2_rn(W3);
    Wh[4] = __float2half2_rn(W4);  Wh[5] = __float2half2_rn(W5);

    const bool interior =
        (x0 >= RAD) && (x0 + TW + RAD <= HW) && (y0 >= RAD) && (y0 + TH + RAD <= HW);

    // ---- Phase V: 256 full 8-out items (1/thread) + 80 quarter-items ----
    {
        int g = tid / INW;               // 0 or 1 (8-row group)
        int c = tid - g * INW;
        int ob = 8 * g;
        int gyb = y0 + ob - RAD;
        int gx = x0 - RAD + c;
        bool xok = interior || ((gx >= 0) && (gx < HW));
        const float* prow = pp + (size_t)gyb * HW + gx;
        const float* trow = tt + (size_t)gyb * HW + gx;
        if (interior) vcol<true , 8>(prow, trow, xok, gyb, c, ob, hb01, hb23, Wb);
        else          vcol<false, 8>(prow, trow, xok, gyb, c, ob, hb01, hb23, Wb);

        if (tid >= 176) {
            int hh = tid - 176;              // 0..79
            int c2 = 118 + (hh >> 2);        // column 118..137
            int ob2 = 8 + 2 * (hh & 3);      // rows 8,10,12,14 (+1)
            int gyb2 = y0 + ob2 - RAD;
            int gx2 = x0 - RAD + c2;
            bool xok2 = interior || ((gx2 >= 0) && (gx2 < HW));
            const float* prow2 = pp + (size_t)gyb2 * HW + gx2;
            const float* trow2 = tt + (size_t)gyb2 * HW + gx2;
            if (interior) vcol<true , 2>(prow2, trow2, xok2, gyb2, c2, ob2, hb01, hb23, Wb);
            else          vcol<false, 2>(prow2, trow2, xok2, gyb2, c2, ob2, hb01, hb23, Wb);
        }
    }
    __syncthreads();

    // ---- Phase H: 8 outputs/thread; 16 rows x 16 x-groups = 256 items ----
    const float C1 = 0.0001f;
    const float C2 = 0.0009f;
    float local = 0.f;
    {
        int r = tid & 15;                   // row
        int xg = tid >> 4;                  // 0..15
        int Xb = xg << 3;                   // x base in u32 units (8 px)
        const unsigned int* rb01 = hb01 + r * HBW + Xb;
        const unsigned int* rb23 = hb23 + r * HBW + Xb;

        // Load 18 positions as 5 x uint4 per array (20 slots, 18 used).
        unsigned int v01[20], v23[20];
#pragma unroll
        for (int q = 0; q < 5; q++) {
            uint4 u = *(const uint4*)(rb01 + 4 * q);
            v01[4*q] = u.x; v01[4*q+1] = u.y; v01[4*q+2] = u.z; v01[4*q+3] = u.w;
            uint4 w = *(const uint4*)(rb23 + 4 * q);
            v23[4*q] = w.x; v23[4*q+1] = w.y; v23[4*q+2] = w.z; v23[4*q+3] = w.w;
        }

        __half2 a01h[8], a23h[8];
#pragma unroll
        for (int j = 0; j < 8; j++) {
            a01h[j] = __float2half2_rn(0.f);
            a23h[j] = __float2half2_rn(0.f);
        }

#pragma unroll
        for (int i = 0; i < 18; i++) {
            __half2 hv01 = *reinterpret_cast<const __half2*>(&v01[i]);
            __half2 hv23 = *reinterpret_cast<const __half2*>(&v23[i]);
#pragma unroll
            for (int j = 0; j < 8; j++) {
                int k = i - j;
                if (k >= 0 && k <= 10) {
                    a01h[j] = __hfma2(Wh[WIDX(k)], hv01, a01h[j]);
                    a23h[j] = __hfma2(Wh[WIDX(k)], hv23, a23h[j]);
                }
            }
        }

#pragma unroll
        for (int j = 0; j < 8; j++) {
            float m1 = __low2float(a01h[j])  * INV_S;
            float m2 = __high2float(a01h[j]) * INV_S;
            float cs = __low2float(a23h[j])  * INV_S;
            float cd = __high2float(a23h[j]) * INV_S;
            float m1s = m1 * m1;
            float m2s = m2 * m2;
            float m12 = m1 * m2;
            float ept   = 0.25f * (cs - cd);     // E[pt]
            float epptt = 0.5f  * (cs + cd);     // E[pp]+E[tt]
            float s12  = ept - m12;
            float ssum = epptt - m1s - m2s;
            float num = (2.0f * m12 + C1) * (2.0f * s12 + C2);
            float den = (m1s + m2s + C1) * (ssum + C2);
            local += __fdividef(num, den);
        }
    }

    // ---- Block reduction -> partial; last block reduces globally ----
#pragma unroll
    for (int off = 16; off > 0; off >>= 1)
        local += __shfl_down_sync(0xffffffffu, local, off);
    if ((tid & 31) == 0) red[tid >> 5] = local;
    __syncthreads();
    if (tid == 0) {
        float v = red[0] + red[1] + red[2] + red[3]
                + red[4] + red[5] + red[6] + red[7];
        int bid = (blockIdx.z * gridDim.y + blockIdx.y) * gridDim.x + blockIdx.x;
        g_partials[bid] = v;
        __threadfence();
        unsigned int n = atomicAdd(&g_counter, 1u);
        s_last = (n == NBLOCKS - 1u);
    }
    __syncthreads();

    if (s_last) {
        __threadfence();
        __shared__ double dred[8];
        const float4* __restrict__ p4 = (const float4*)g_partials;
        double acc = 0.0;
#pragma unroll
        for (int i = 0; i < NBLOCKS / 4 / 256; i++) {   // 6 iterations
            float4 v = p4[i * 256 + tid];
            acc += (double)v.x + (double)v.y + (double)v.z + (double)v.w;
        }
#pragma unroll
        for (int off = 16; off > 0; off >>= 1)
            acc += __shfl_down_sync(0xffffffffu, acc, off);
        if ((tid & 31) == 0) dred[tid >> 5] = acc;
        __syncthreads();
        if (tid == 0) {
            double s = dred[0] + dred[1] + dred[2] + dred[3]
                     + dred[4] + dred[5] + dred[6] + dred[7];
            out[0] = 1.0f - (float)(s * (double)inv_count);
            g_counter = 0;
        }
    }
}

extern "C" void kernel_launch(void* const* d_in, const int* in_sizes, int n_in,
                              void* d_out, int out_size) {
    const float* pred = (const float*)d_in[0];
    const float* target = (const float*)d_in[1];
    float* out = (float*)d_out;

    const int total = in_sizes[0];                 // N*C*H*W
    const int nplanes = total / PLANE_ELEMS;       // 48

    const size_t smem = sizeof(unsigned int) * 2 * TH * HBW;   // 18944 B
    cudaFuncSetAttribute(ssim_main_kernel,
                         cudaFuncAttributeMaxDynamicSharedMemorySize, (int)smem);

    dim3 grid(HW / TW, HW / TH, nplanes);          // (4, 32, 48) = 6144 blocks
    ssim_main_kernel<<<grid, 256, smem>>>(pred, target, out, 1.0f / (float)total);
}